// round 4
// baseline (speedup 1.0000x reference)
#include <cuda_runtime.h>

// LoRALayerNorm: x [B=2, S=4096, N=8192] fp32
// scale[i] = SCALING * sum_r A_s[i,r] * B_s[r,i]
// shift[i] = SCALING * sum_r A_h[i,r] * B_h[r,i]
// out = layernorm(x, last dim) * scale + shift

#define N_FEAT 8192
#define N_ROWS 8192
#define RANK 4
#define SCALING_F 2.0f   // ALPHA/RANK = 8/4
#define EPS_F 1e-5f

#define TPB 512                 // threads per block (row kernel)
#define VEC_PER_THREAD 4        // 4 x float4 = 16 floats/thread; 512*16 = 8192

__device__ float g_scale[N_FEAT];
__device__ float g_shift[N_FEAT];

// ---------------------------------------------------------------------------
// Kernel 1: low-rank diagonal -> scale/shift vectors
// ---------------------------------------------------------------------------
__global__ void compute_vectors_kernel(const float* __restrict__ sA,
                                       const float* __restrict__ sB,
                                       const float* __restrict__ hA,
                                       const float* __restrict__ hB) {
    int i = blockIdx.x * blockDim.x + threadIdx.x;
    if (i >= N_FEAT) return;
    // A: [N, RANK] row-major; B: [RANK, N] row-major
    float4 a_s = *reinterpret_cast<const float4*>(sA + i * RANK);
    float4 a_h = *reinterpret_cast<const float4*>(hA + i * RANK);
    float sc = a_s.x * sB[0 * N_FEAT + i]
             + a_s.y * sB[1 * N_FEAT + i]
             + a_s.z * sB[2 * N_FEAT + i]
             + a_s.w * sB[3 * N_FEAT + i];
    float sh = a_h.x * hB[0 * N_FEAT + i]
             + a_h.y * hB[1 * N_FEAT + i]
             + a_h.z * hB[2 * N_FEAT + i]
             + a_h.w * hB[3 * N_FEAT + i];
    g_scale[i] = sc * SCALING_F;
    g_shift[i] = sh * SCALING_F;
}

// ---------------------------------------------------------------------------
// Kernel 2: one CTA per row. Low register pressure: x is NOT kept in
// registers across the reduction; the epilogue re-reads it from L1
// (4 CTAs x 32KB/row = 128KB fits the 228KB L1). This allows 4 resident
// CTAs/SM (100% occupancy) so the reduction-barrier shadow of one CTA is
// covered by the load phase of another.
// ---------------------------------------------------------------------------
__global__ __launch_bounds__(TPB, 4)
void lora_layernorm_kernel(const float* __restrict__ x,
                           float* __restrict__ out) {
    const int row = blockIdx.x;
    const int tid = threadIdx.x;
    const float4* xrow = reinterpret_cast<const float4*>(x + (size_t)row * N_FEAT);
    float4* orow = reinterpret_cast<float4*>(out + (size_t)row * N_FEAT);

    // Pass 1: load (default caching -> stays in L1 for the epilogue re-read)
    float sum = 0.0f, sumsq = 0.0f;
#pragma unroll
    for (int k = 0; k < VEC_PER_THREAD; k++) {
        float4 t = __ldg(&xrow[tid + k * TPB]);
        sum += t.x + t.y + t.z + t.w;
        sumsq += t.x * t.x + t.y * t.y + t.z * t.z + t.w * t.w;
    }

    // Warp reduce
#pragma unroll
    for (int off = 16; off > 0; off >>= 1) {
        sum += __shfl_xor_sync(0xffffffffu, sum, off);
        sumsq += __shfl_xor_sync(0xffffffffu, sumsq, off);
    }

    __shared__ float s_sum[TPB / 32];
    __shared__ float s_sumsq[TPB / 32];
    __shared__ float s_mean, s_rstd;
    const int wid = tid >> 5;
    const int lane = tid & 31;
    if (lane == 0) {
        s_sum[wid] = sum;
        s_sumsq[wid] = sumsq;
    }
    __syncthreads();
    if (wid == 0) {
        float a = (lane < TPB / 32) ? s_sum[lane] : 0.0f;
        float b = (lane < TPB / 32) ? s_sumsq[lane] : 0.0f;
#pragma unroll
        for (int off = 8; off > 0; off >>= 1) {
            a += __shfl_xor_sync(0xffffffffu, a, off);
            b += __shfl_xor_sync(0xffffffffu, b, off);
        }
        if (lane == 0) {
            float mean = a * (1.0f / N_FEAT);
            float var = b * (1.0f / N_FEAT) - mean * mean;
            s_mean = mean;
            s_rstd = rsqrtf(var + EPS_F);
        }
    }
    __syncthreads();
    const float mean = s_mean;
    const float rstd = s_rstd;

    // Pass 2: re-read x (L1 hit), apply affine, streaming store.
    const float4* scv = reinterpret_cast<const float4*>(g_scale);
    const float4* shv = reinterpret_cast<const float4*>(g_shift);
#pragma unroll
    for (int k = 0; k < VEC_PER_THREAD; k++) {
        int idx = tid + k * TPB;
        float4 t = __ldg(&xrow[idx]);
        float4 sc = __ldg(&scv[idx]);
        float4 sh = __ldg(&shv[idx]);
        float4 o;
        o.x = (t.x - mean) * rstd * sc.x + sh.x;
        o.y = (t.y - mean) * rstd * sc.y + sh.y;
        o.z = (t.z - mean) * rstd * sc.z + sh.z;
        o.w = (t.w - mean) * rstd * sc.w + sh.w;
        __stcs(&orow[idx], o);
    }
}

// ---------------------------------------------------------------------------
extern "C" void kernel_launch(void* const* d_in, const int* in_sizes, int n_in,
                              void* d_out, int out_size) {
    const float* x = (const float*)d_in[0];
    const float* sA = (const float*)d_in[1];
    const float* sB = (const float*)d_in[2];
    const float* hA = (const float*)d_in[3];
    const float* hB = (const float*)d_in[4];
    float* out = (float*)d_out;

    compute_vectors_kernel<<<N_FEAT / 256, 256>>>(sA, sB, hA, hB);
    lora_layernorm_kernel<<<N_ROWS, TPB>>>(x, out);
}

// round 5
// speedup vs baseline: 1.0189x; 1.0189x over previous
#include <cuda_runtime.h>

// LoRALayerNorm: x [B=2, S=4096, N=8192] fp32
// scale[i] = SCALING * sum_r A_s[i,r] * B_s[r,i]
// shift[i] = SCALING * sum_r A_h[i,r] * B_h[r,i]
// out = layernorm(x, last dim) * scale + shift

#define N_FEAT 8192
#define N_ROWS 8192
#define RANK 4
#define SCALING_F 2.0f   // ALPHA/RANK = 8/4
#define EPS_F 1e-5f

#define TPB 512          // threads per block
#define VPT 4            // float4 per thread per row: 512*4*4 = 8192 floats

__device__ float g_scale[N_FEAT];
__device__ float g_shift[N_FEAT];

// ---------------------------------------------------------------------------
// Kernel 1: low-rank diagonal -> scale/shift vectors
// ---------------------------------------------------------------------------
__global__ void compute_vectors_kernel(const float* __restrict__ sA,
                                       const float* __restrict__ sB,
                                       const float* __restrict__ hA,
                                       const float* __restrict__ hB) {
    int i = blockIdx.x * blockDim.x + threadIdx.x;
    if (i >= N_FEAT) return;
    float4 a_s = *reinterpret_cast<const float4*>(sA + i * RANK);
    float4 a_h = *reinterpret_cast<const float4*>(hA + i * RANK);
    float sc = a_s.x * sB[0 * N_FEAT + i]
             + a_s.y * sB[1 * N_FEAT + i]
             + a_s.z * sB[2 * N_FEAT + i]
             + a_s.w * sB[3 * N_FEAT + i];
    float sh = a_h.x * hB[0 * N_FEAT + i]
             + a_h.y * hB[1 * N_FEAT + i]
             + a_h.z * hB[2 * N_FEAT + i]
             + a_h.w * hB[3 * N_FEAT + i];
    g_scale[i] = sc * SCALING_F;
    g_shift[i] = sh * SCALING_F;
}

// ---------------------------------------------------------------------------
// Kernel 2: TWO rows per CTA, fully register-resident (single DRAM read).
// 8 LDG.128 per thread front-batched before the single reduce barrier:
// row1's in-flight loads hide row0's reduction latency, and one barrier
// amortizes over two rows. scale/shift loaded once, applied to both rows.
// ---------------------------------------------------------------------------
__global__ __launch_bounds__(TPB, 2)
void lora_layernorm2_kernel(const float* __restrict__ x,
                            float* __restrict__ out) {
    const int tid = threadIdx.x;
    const size_t r0 = (size_t)blockIdx.x * 2;
    const float4* x0 = reinterpret_cast<const float4*>(x + r0 * N_FEAT);
    const float4* x1 = reinterpret_cast<const float4*>(x + (r0 + 1) * N_FEAT);
    float4* o0 = reinterpret_cast<float4*>(out + r0 * N_FEAT);
    float4* o1 = reinterpret_cast<float4*>(out + (r0 + 1) * N_FEAT);

    // Front-batched loads: 8 outstanding LDG.128 per thread.
    float4 v0[VPT], v1[VPT];
#pragma unroll
    for (int k = 0; k < VPT; k++) v0[k] = __ldcs(&x0[tid + k * TPB]);
#pragma unroll
    for (int k = 0; k < VPT; k++) v1[k] = __ldcs(&x1[tid + k * TPB]);

    float s0 = 0.f, q0 = 0.f, s1 = 0.f, q1 = 0.f;
#pragma unroll
    for (int k = 0; k < VPT; k++) {
        float4 t = v0[k];
        s0 += t.x + t.y + t.z + t.w;
        q0 += t.x * t.x + t.y * t.y + t.z * t.z + t.w * t.w;
    }
#pragma unroll
    for (int k = 0; k < VPT; k++) {
        float4 t = v1[k];
        s1 += t.x + t.y + t.z + t.w;
        q1 += t.x * t.x + t.y * t.y + t.z * t.z + t.w * t.w;
    }

    // Warp reduce all four quantities.
#pragma unroll
    for (int off = 16; off > 0; off >>= 1) {
        s0 += __shfl_xor_sync(0xffffffffu, s0, off);
        q0 += __shfl_xor_sync(0xffffffffu, q0, off);
        s1 += __shfl_xor_sync(0xffffffffu, s1, off);
        q1 += __shfl_xor_sync(0xffffffffu, q1, off);
    }

    __shared__ float s_red[4][TPB / 32];   // [s0,q0,s1,q1] x 16 warps
    __shared__ float s_tot[4];
    const int wid = tid >> 5;
    const int lane = tid & 31;
    if (lane == 0) {
        s_red[0][wid] = s0;
        s_red[1][wid] = q0;
        s_red[2][wid] = s1;
        s_red[3][wid] = q1;
    }
    __syncthreads();
    // Warps 0..3 each reduce one of the four arrays.
    if (wid < 4) {
        float a = (lane < TPB / 32) ? s_red[wid][lane] : 0.0f;
#pragma unroll
        for (int off = 8; off > 0; off >>= 1)
            a += __shfl_xor_sync(0xffffffffu, a, off);
        if (lane == 0) s_tot[wid] = a;
    }
    __syncthreads();

    const float invN = 1.0f / N_FEAT;
    const float mean0 = s_tot[0] * invN;
    const float mean1 = s_tot[2] * invN;
    const float rstd0 = rsqrtf(s_tot[1] * invN - mean0 * mean0 + EPS_F);
    const float rstd1 = rsqrtf(s_tot[3] * invN - mean1 * mean1 + EPS_F);

    // Epilogue: sc/sh loaded once, applied to both rows.
    const float4* scv = reinterpret_cast<const float4*>(g_scale);
    const float4* shv = reinterpret_cast<const float4*>(g_shift);
#pragma unroll
    for (int k = 0; k < VPT; k++) {
        const int idx = tid + k * TPB;
        float4 sc = __ldg(&scv[idx]);
        float4 sh = __ldg(&shv[idx]);
        float4 t0 = v0[k];
        float4 t1 = v1[k];
        float4 a, b;
        a.x = (t0.x - mean0) * rstd0 * sc.x + sh.x;
        a.y = (t0.y - mean0) * rstd0 * sc.y + sh.y;
        a.z = (t0.z - mean0) * rstd0 * sc.z + sh.z;
        a.w = (t0.w - mean0) * rstd0 * sc.w + sh.w;
        b.x = (t1.x - mean1) * rstd1 * sc.x + sh.x;
        b.y = (t1.y - mean1) * rstd1 * sc.y + sh.y;
        b.z = (t1.z - mean1) * rstd1 * sc.z + sh.z;
        b.w = (t1.w - mean1) * rstd1 * sc.w + sh.w;
        __stcs(&o0[idx], a);
        __stcs(&o1[idx], b);
    }
}

// ---------------------------------------------------------------------------
extern "C" void kernel_launch(void* const* d_in, const int* in_sizes, int n_in,
                              void* d_out, int out_size) {
    const float* x = (const float*)d_in[0];
    const float* sA = (const float*)d_in[1];
    const float* sB = (const float*)d_in[2];
    const float* hA = (const float*)d_in[3];
    const float* hB = (const float*)d_in[4];
    float* out = (float*)d_out;

    compute_vectors_kernel<<<N_FEAT / 256, 256>>>(sA, sB, hA, hB);
    lora_layernorm2_kernel<<<N_ROWS / 2, TPB>>>(x, out);
}